// round 12
// baseline (speedup 1.0000x reference)
#include <cuda_runtime.h>
#include <cuda_bf16.h>
#include <cstdint>

// x:   [B=64, C=12, 224, 224] fp32
// w:   [C=12, E=768] fp32
// out: [B=64, P=196, E=768] fp32
//
// R7 skeleton (best so far: 2x2 patch block, warp=channel, 8 staged LDG.128
// per thread, dual shuffle-reduce, dual-output epilogue) with two changes:
//  1) w prefetched to smem via cp.async at kernel entry (zero register cost,
//     hidden under phase-1's DRAM window, drained by the existing barrier).
//  2) x loaded with __ldcg (L2-only): streaming data stops thrashing L1.

#define IMG    224
#define NP     14
#define C_IN   12
#define EMBED  768
#define NTH    384
#define WSZ    (C_IN * EMBED)     // 9216 floats = 36 KB

__device__ __forceinline__ float4 ldcg4(const float* p) {
    return __ldcg(reinterpret_cast<const float4*>(p));
}

__global__ __launch_bounds__(NTH, 3) void patch_block_wsm_kernel(
    const float* __restrict__ x,
    const float* __restrict__ w,
    float* __restrict__ out)
{
    __shared__ __align__(16) float wsm[WSZ];          // 36 KB
    __shared__ float pooled[C_IN][4];

    const int pp  = blockIdx.x;        // patch-col pair 0..6
    const int pr  = blockIdx.y;        // patch-row pair 0..6
    const int b   = blockIdx.z;        // 0..63
    const int t   = threadIdx.x;
    const int warp = t >> 5;           // channel 0..11
    const int lane = t & 31;
    const int q8  = lane & 7;          // float4 col within the 32-float row
    const int rh  = lane >> 3;         // row phase 0..3

    // ---- Fire w -> smem prefetch (6 x 16B per thread, fire-and-forget) ----
    {
        const uint32_t wdst = (uint32_t)__cvta_generic_to_shared(&wsm[t * 4]);
        const float*   wsrc = w + t * 4;
        #pragma unroll
        for (int k = 0; k < 6; ++k)
            asm volatile("cp.async.cg.shared.global [%0], [%1], 16;"
                         :: "r"(wdst + k * NTH * 16), "l"(wsrc + k * NTH * 4)
                         : "memory");
        asm volatile("cp.async.commit_group;" ::: "memory");
    }

    // ---- Phase 1: pool a 32x32 region of channel `warp` (8 staged LDG) ----
    const float* base = x
        + (((size_t)(b * C_IN + warp)) * IMG + (size_t)pr * 32 + rh) * IMG
        + (size_t)pp * 32 + q8 * 4;

    float4 u0 = ldcg4(base + (size_t)(4 * 0) * IMG);
    float4 u1 = ldcg4(base + (size_t)(4 * 1) * IMG);
    float4 u2 = ldcg4(base + (size_t)(4 * 2) * IMG);
    float4 u3 = ldcg4(base + (size_t)(4 * 3) * IMG);
    float4 d0 = ldcg4(base + (size_t)(4 * 4) * IMG);
    float4 d1 = ldcg4(base + (size_t)(4 * 5) * IMG);
    float4 d2 = ldcg4(base + (size_t)(4 * 6) * IMG);
    float4 d3 = ldcg4(base + (size_t)(4 * 7) * IMG);

    float st = (((u0.x + u0.y) + (u0.z + u0.w)) + ((u1.x + u1.y) + (u1.z + u1.w)))
             + (((u2.x + u2.y) + (u2.z + u2.w)) + ((u3.x + u3.y) + (u3.z + u3.w)));
    float sb = (((d0.x + d0.y) + (d0.z + d0.w)) + ((d1.x + d1.y) + (d1.z + d1.w)))
             + (((d2.x + d2.y) + (d2.z + d2.w)) + ((d3.x + d3.y) + (d3.z + d3.w)));

    // Fold lane bits 0,1 (float4 cols within a patch) and 3,4 (row phases);
    // bit 2 (q8>>2) = patch column survives.
    st += __shfl_xor_sync(0xffffffffu, st, 1);
    sb += __shfl_xor_sync(0xffffffffu, sb, 1);
    st += __shfl_xor_sync(0xffffffffu, st, 2);
    sb += __shfl_xor_sync(0xffffffffu, sb, 2);
    st += __shfl_xor_sync(0xffffffffu, st, 8);
    sb += __shfl_xor_sync(0xffffffffu, sb, 8);
    st += __shfl_xor_sync(0xffffffffu, st, 16);
    sb += __shfl_xor_sync(0xffffffffu, sb, 16);

    if ((lane & 27) == 0) {            // lanes 0 and 4
        const int pc = (lane >> 2) & 1;
        pooled[warp][pc]     = st;     // top patch row
        pooled[warp][2 + pc] = sb;     // bottom patch row
    }

    // w copies are long since arrived (fired before ~1000-cycle phase 1);
    // wait + the single barrier makes them (and pooled) visible to all.
    asm volatile("cp.async.wait_group 0;" ::: "memory");
    __syncthreads();

    // ---- Phase 2: w from smem (conflict-free LDS.128), two outputs ----
    const int e4 = t % 192;            // output float4 slot
    const int lr = t / 192;            // local patch row 0/1 (uniform per warp)

    float4 acc0 = make_float4(0.f, 0.f, 0.f, 0.f);  // patch col 0
    float4 acc1 = make_float4(0.f, 0.f, 0.f, 0.f);  // patch col 1
    #pragma unroll
    for (int c = 0; c < C_IN; ++c) {
        const float4 wv = *reinterpret_cast<const float4*>(&wsm[c * EMBED + e4 * 4]);
        const float p0 = pooled[c][lr * 2 + 0];
        const float p1 = pooled[c][lr * 2 + 1];
        acc0.x = fmaf(p0, wv.x, acc0.x);  acc1.x = fmaf(p1, wv.x, acc1.x);
        acc0.y = fmaf(p0, wv.y, acc0.y);  acc1.y = fmaf(p1, wv.y, acc1.y);
        acc0.z = fmaf(p0, wv.z, acc0.z);  acc1.z = fmaf(p1, wv.z, acc1.z);
        acc0.w = fmaf(p0, wv.w, acc0.w);  acc1.w = fmaf(p1, wv.w, acc1.w);
    }

    const int pi = pr * 2 + lr;        // global patch row
    const int pj = pp * 2;             // global patch col (even)
    float* o = out + ((size_t)b * (NP * NP) + (size_t)pi * NP + pj) * EMBED + e4 * 4;
    *reinterpret_cast<float4*>(o)         = acc0;   // patch (pi, pj)
    *reinterpret_cast<float4*>(o + EMBED) = acc1;   // patch (pi, pj+1)
}

extern "C" void kernel_launch(void* const* d_in, const int* in_sizes, int n_in,
                              void* d_out, int out_size)
{
    const float* x = (const float*)d_in[0];
    const float* w = (const float*)d_in[1];
    float* out = (float*)d_out;

    dim3 grid(7, 7, 64);   // 3136 CTAs
    patch_block_wsm_kernel<<<grid, NTH>>>(x, w, out);
}

// round 13
// speedup vs baseline: 1.1053x; 1.1053x over previous
#include <cuda_runtime.h>
#include <cuda_bf16.h>
#include <cstdint>

// x:   [B=64, C=12, 224, 224] fp32
// w:   [C=12, E=768] fp32
// out: [B=64, P=196, E=768] fp32
//
// R7 (best: 31.55us kernel, DRAM 70.1%) with ONE change: x loads use __ldcg
// (L2-only). x is pure streaming (zero reuse) and was thrashing w out of L1;
// with the bypass, w stays L1-resident and the per-CTA phase-2 tail shrinks.
//
// CTA = 2x2 patch block (32x32 pixels x 12 channels = 48 KB of x).
// Phase 1: warp = channel, 8 independent full-line float4 loads per thread,
//          dual shuffle-reduce -> pooled[12][4].
// Phase 2: each thread loads w[:, e4] once (L1-hot) and emits TWO outputs.

#define IMG    224
#define NP     14
#define C_IN   12
#define EMBED  768
#define NTH    384

__device__ __forceinline__ float4 ldcg4(const float* p) {
    return __ldcg(reinterpret_cast<const float4*>(p));
}

__global__ __launch_bounds__(NTH, 3) void patch_block_ldcg_kernel(
    const float* __restrict__ x,
    const float* __restrict__ w,
    float* __restrict__ out)
{
    const int pp  = blockIdx.x;        // patch-col pair 0..6
    const int pr  = blockIdx.y;        // patch-row pair 0..6
    const int b   = blockIdx.z;        // 0..63
    const int t   = threadIdx.x;
    const int warp = t >> 5;           // channel 0..11
    const int lane = t & 31;
    const int q8  = lane & 7;          // float4 col within the 32-float row
    const int rh  = lane >> 3;         // row phase 0..3

    __shared__ float pooled[C_IN][4];  // [channel][prow*2 + pcol]

    // ---- Phase 1: pool a 32x32 region of channel `warp` ----
    // Thread loads rows rh + 4k (k=0..7) at float4-col q8: 8 independent
    // LDG.128 (L2-only), each warp row segment = one full 128B line.
    const float* base = x
        + (((size_t)(b * C_IN + warp)) * IMG + (size_t)pr * 32 + rh) * IMG
        + (size_t)pp * 32 + q8 * 4;

    float4 u0 = ldcg4(base + (size_t)(4 * 0) * IMG);
    float4 u1 = ldcg4(base + (size_t)(4 * 1) * IMG);
    float4 u2 = ldcg4(base + (size_t)(4 * 2) * IMG);
    float4 u3 = ldcg4(base + (size_t)(4 * 3) * IMG);
    float4 d0 = ldcg4(base + (size_t)(4 * 4) * IMG);
    float4 d1 = ldcg4(base + (size_t)(4 * 5) * IMG);
    float4 d2 = ldcg4(base + (size_t)(4 * 6) * IMG);
    float4 d3 = ldcg4(base + (size_t)(4 * 7) * IMG);

    float st = (((u0.x + u0.y) + (u0.z + u0.w)) + ((u1.x + u1.y) + (u1.z + u1.w)))
             + (((u2.x + u2.y) + (u2.z + u2.w)) + ((u3.x + u3.y) + (u3.z + u3.w)));
    float sb = (((d0.x + d0.y) + (d0.z + d0.w)) + ((d1.x + d1.y) + (d1.z + d1.w)))
             + (((d2.x + d2.y) + (d2.z + d2.w)) + ((d3.x + d3.y) + (d3.z + d3.w)));

    // Fold lane bits 0,1 (float4 cols within a patch) and 3,4 (row phases);
    // bit 2 (q8>>2) = patch column survives.
    st += __shfl_xor_sync(0xffffffffu, st, 1);
    sb += __shfl_xor_sync(0xffffffffu, sb, 1);
    st += __shfl_xor_sync(0xffffffffu, st, 2);
    sb += __shfl_xor_sync(0xffffffffu, sb, 2);
    st += __shfl_xor_sync(0xffffffffu, st, 8);
    sb += __shfl_xor_sync(0xffffffffu, sb, 8);
    st += __shfl_xor_sync(0xffffffffu, st, 16);
    sb += __shfl_xor_sync(0xffffffffu, sb, 16);

    if ((lane & 27) == 0) {            // lanes 0 and 4
        const int pc = (lane >> 2) & 1;
        pooled[warp][pc]     = st;     // top patch row
        pooled[warp][2 + pc] = sb;     // bottom patch row
    }
    __syncthreads();

    // ---- Phase 2: one w column read serves two patch outputs ----
    const int e4 = t % 192;            // output float4 slot
    const int lr = t / 192;            // local patch row 0/1 (uniform per warp)

    float4 acc0 = make_float4(0.f, 0.f, 0.f, 0.f);  // patch col 0
    float4 acc1 = make_float4(0.f, 0.f, 0.f, 0.f);  // patch col 1
    #pragma unroll
    for (int c = 0; c < C_IN; ++c) {
        const float4 wv = *reinterpret_cast<const float4*>(&w[c * EMBED + e4 * 4]);
        const float p0 = pooled[c][lr * 2 + 0];
        const float p1 = pooled[c][lr * 2 + 1];
        acc0.x = fmaf(p0, wv.x, acc0.x);  acc1.x = fmaf(p1, wv.x, acc1.x);
        acc0.y = fmaf(p0, wv.y, acc0.y);  acc1.y = fmaf(p1, wv.y, acc1.y);
        acc0.z = fmaf(p0, wv.z, acc0.z);  acc1.z = fmaf(p1, wv.z, acc1.z);
        acc0.w = fmaf(p0, wv.w, acc0.w);  acc1.w = fmaf(p1, wv.w, acc1.w);
    }

    const int pi = pr * 2 + lr;        // global patch row
    const int pj = pp * 2;             // global patch col (even)
    float* o = out + ((size_t)b * (NP * NP) + (size_t)pi * NP + pj) * EMBED + e4 * 4;
    *reinterpret_cast<float4*>(o)         = acc0;   // patch (pi, pj)
    *reinterpret_cast<float4*>(o + EMBED) = acc1;   // patch (pi, pj+1)
}

extern "C" void kernel_launch(void* const* d_in, const int* in_sizes, int n_in,
                              void* d_out, int out_size)
{
    const float* x = (const float*)d_in[0];
    const float* w = (const float*)d_in[1];
    float* out = (float*)d_out;

    dim3 grid(7, 7, 64);   // 3136 CTAs
    patch_block_ldcg_kernel<<<grid, NTH>>>(x, w, out);
}